// round 15
// baseline (speedup 1.0000x reference)
#include <cuda_runtime.h>
#include <cuda_fp16.h>
#include <cstdint>

#define NNODES 100000
#define NEDGES 1600000
#define NF4    (NNODES * 16)          // float4 slots per fp32 plane (== NEDGES)
#define PCSR   (NEDGES + 3 * NNODES)  // padded CSR capacity
#define NROWS  (NNODES + 1)           // +1 zero row for dummy edges
#define NBLK   196                    // scan blocks: 196*512 >= NNODES

// ---------------------------------------------------------------------------
// Device-global scratch (no allocation allowed). Planes store S_k = dis*feat_k.
// Invariant: g_deg is all-zero on entry (zero at load; scan re-zeroes).
__device__ __half2 g_feat[4][NROWS * 32];     // planes 0..3 fp16 (row NNODES = 0)
__device__ __align__(16) int g_csr[PCSR];     // src index only; pads = NNODES
__device__ int     g_off[NNODES + 1];         // padded offsets (mult of 4)
__device__ int     g_cursor[NNODES];
__device__ int     g_deg[NNODES];
__device__ float   g_dis[NNODES];             // 1/sqrt(max(deg,1))
__device__ float   g_dis2[NNODES];            // 1/max(deg,1)
__device__ float   g_invdis[NNODES];          // sqrt(max(deg,1))
__device__ unsigned long long g_state[NBLK];  // lookback: flag<<62 | sum
__device__ unsigned g_ticket;
__device__ int     g_idx64;

// ---------------------------------------------------------------------------
// single tiny block: detect index width, zero scan state/ticket, zero row NNODES
__global__ void detect_kernel(const int* __restrict__ ei32) {
    int t = threadIdx.x;
    if (t < NBLK) g_state[t] = 0ULL;
    if (t == 255) g_ticket = 0;
    if (t < 128) {  // zero row NNODES of all 4 planes (4 planes x 32 half2)
        int plane = t >> 5, slot = t & 31;
        g_feat[plane][NNODES * 32 + slot] = __floats2half2_rn(0.f, 0.f);
    }
    if (t < 32) {
        int nz = 0;
        for (int q = t; q < 2048; q += 32) nz |= ei32[2 * q + 1];
        unsigned m = __ballot_sync(0xffffffffu, nz != 0);
        if (t == 0) g_idx64 = (m == 0) ? 1 : 0;
    }
}

// degree count: 4 dst per thread, wide loads for MLP
__global__ void deg_kernel(const void* __restrict__ eiv) {
    int t = blockIdx.x * blockDim.x + threadIdx.x;
    int e0 = 4 * t;
    if (e0 >= NEDGES) return;
    int d0, d1, d2, d3;
    if (g_idx64) {
        const longlong2* p = (const longlong2*)eiv;           // dst half base
        longlong2 a = __ldg(&p[(NEDGES >> 1) + 2 * t]);
        longlong2 b = __ldg(&p[(NEDGES >> 1) + 2 * t + 1]);
        d0 = (int)a.x; d1 = (int)a.y; d2 = (int)b.x; d3 = (int)b.y;
    } else {
        const int4* p = (const int4*)eiv;
        int4 a = __ldg(&p[(NEDGES >> 2) + t]);
        d0 = a.x; d1 = a.y; d2 = a.z; d3 = a.w;
    }
    atomicAdd(&g_deg[d0], 1);
    atomicAdd(&g_deg[d1], 1);
    atomicAdd(&g_deg[d2], 1);
    atomicAdd(&g_deg[d3], 1);
}

// ---------------------------------------------------------------------------
// Single-pass decoupled-lookback exclusive scan of padded degrees.
// Writes cursor, dis/dis2/invdis, CSR pad entries; re-zeroes g_deg.
__global__ void scan_kernel() {
    __shared__ int s[512];
    __shared__ int sbid, sexcl;
    int tid = threadIdx.x;
    if (tid == 0) sbid = (int)atomicAdd(&g_ticket, 1u);
    __syncthreads();
    int bid = sbid;
    int i = bid * 512 + tid;

    int deg  = (i < NNODES) ? g_deg[i] : 0;
    int pdeg = (deg + 3) & ~3;

    s[tid] = pdeg; __syncthreads();
    for (int st = 1; st < 512; st <<= 1) {
        int a = (tid >= st) ? s[tid - st] : 0;
        __syncthreads();
        s[tid] += a;
        __syncthreads();
    }
    int incl = s[tid], total = s[511];

    if (tid == 0) {
        if (bid == 0) {
            atomicExch(&g_state[0], (2ULL << 62) | (unsigned)total);
            sexcl = 0;
        } else {
            atomicExch(&g_state[bid], (1ULL << 62) | (unsigned)total);
            long long ex = 0; int p = bid - 1;
            while (true) {
                unsigned long long v = atomicAdd(&g_state[p], 0ULL);
                unsigned long long fl = v >> 62;
                if (fl == 2ULL) { ex += (long long)(v & 0xFFFFFFFFULL); break; }
                if (fl == 1ULL) { ex += (long long)(v & 0xFFFFFFFFULL); p--; }
            }
            atomicExch(&g_state[bid], (2ULL << 62) | (unsigned)(ex + total));
            sexcl = (int)ex;
        }
    }
    __syncthreads();

    int off = sexcl + incl - pdeg;   // exclusive, multiple of 4
    if (i < NNODES) {
        g_off[i] = off;
        g_cursor[i] = off;
        float fd = fmaxf((float)deg, 1.0f);
        g_dis[i] = rsqrtf(fd);
        g_dis2[i] = 1.0f / fd;
        g_invdis[i] = sqrtf(fd);
        for (int j = deg; j < pdeg; j++) g_csr[off + j] = NNODES;  // dummy -> zero row
        g_deg[i] = 0;   // restore invariant for next replay
    }
    if (i == NNODES - 1) g_off[NNODES] = off + pdeg;
}

// ---------------------------------------------------------------------------
// fill CSR + init S0 = dis*x; FOUR edges / float4-slots per thread.
// All cold loads hoisted before the atomics for maximum MLP.
// x chunk [4t, 4t+4) never crosses a 16-slot row -> single dis per thread.
__global__ void fill_init_kernel(const void* __restrict__ eiv,
                                 const float4* __restrict__ x4) {
    int t = blockIdx.x * blockDim.x + threadIdx.x;
    int e0 = 4 * t;
    if (e0 >= NEDGES) return;

    int s0, s1, s2, s3, d0, d1, d2, d3;
    float4 v0, v1, v2, v3;
    if (g_idx64) {
        const longlong2* p = (const longlong2*)eiv;
        longlong2 sa = __ldg(&p[2 * t]);
        longlong2 sb = __ldg(&p[2 * t + 1]);
        longlong2 da = __ldg(&p[(NEDGES >> 1) + 2 * t]);
        longlong2 db = __ldg(&p[(NEDGES >> 1) + 2 * t + 1]);
        v0 = __ldg(&x4[e0]);
        v1 = __ldg(&x4[e0 + 1]);
        v2 = __ldg(&x4[e0 + 2]);
        v3 = __ldg(&x4[e0 + 3]);
        s0 = (int)sa.x; s1 = (int)sa.y; s2 = (int)sb.x; s3 = (int)sb.y;
        d0 = (int)da.x; d1 = (int)da.y; d2 = (int)db.x; d3 = (int)db.y;
    } else {
        const int4* p = (const int4*)eiv;
        int4 sa = __ldg(&p[t]);
        int4 da = __ldg(&p[(NEDGES >> 2) + t]);
        v0 = __ldg(&x4[e0]);
        v1 = __ldg(&x4[e0 + 1]);
        v2 = __ldg(&x4[e0 + 2]);
        v3 = __ldg(&x4[e0 + 3]);
        s0 = sa.x; s1 = sa.y; s2 = sa.z; s3 = sa.w;
        d0 = da.x; d1 = da.y; d2 = da.z; d3 = da.w;
    }

    int p0 = atomicAdd(&g_cursor[d0], 1);
    int p1 = atomicAdd(&g_cursor[d1], 1);
    int p2 = atomicAdd(&g_cursor[d2], 1);
    int p3 = atomicAdd(&g_cursor[d3], 1);
    g_csr[p0] = s0;
    g_csr[p1] = s1;
    g_csr[p2] = s2;
    g_csr[p3] = s3;

    // feature init: one node per thread (4-aligned chunk within 16-slot row)
    float dis = __ldg(&g_dis[e0 >> 4]);
    g_feat[0][2 * e0]     = __floats2half2_rn(dis * v0.x, dis * v0.y);
    g_feat[0][2 * e0 + 1] = __floats2half2_rn(dis * v0.z, dis * v0.w);
    g_feat[0][2 * e0 + 2] = __floats2half2_rn(dis * v1.x, dis * v1.y);
    g_feat[0][2 * e0 + 3] = __floats2half2_rn(dis * v1.z, dis * v1.w);
    g_feat[0][2 * e0 + 4] = __floats2half2_rn(dis * v2.x, dis * v2.y);
    g_feat[0][2 * e0 + 5] = __floats2half2_rn(dis * v2.z, dis * v2.w);
    g_feat[0][2 * e0 + 6] = __floats2half2_rn(dis * v3.x, dis * v3.y);
    g_feat[0][2 * e0 + 7] = __floats2half2_rn(dis * v3.z, dis * v3.w);
}

// ---------------------------------------------------------------------------
// Gather core: 8 lanes/node, 16 B/lane, uniform 4-edge bodies, csr quad
// prefetched one body ahead.
__device__ __forceinline__ void acc_row(float2& a0, float2& a1, float2& a2, float2& a3,
                                        uint4 r) {
    float2 f0 = __half22float2(*reinterpret_cast<__half2*>(&r.x));
    float2 f1 = __half22float2(*reinterpret_cast<__half2*>(&r.y));
    float2 f2 = __half22float2(*reinterpret_cast<__half2*>(&r.z));
    float2 f3 = __half22float2(*reinterpret_cast<__half2*>(&r.w));
    a0.x += f0.x; a0.y += f0.y;
    a1.x += f1.x; a1.y += f1.y;
    a2.x += f2.x; a2.y += f2.y;
    a3.x += f3.x; a3.y += f3.y;
}

__device__ __forceinline__ void gather_accum(int node, int sl,
                                             const uint4* __restrict__ fp,
                                             float2& a0, float2& a1,
                                             float2& a2, float2& a3) {
    int beg = __ldg(&g_off[node]), end = __ldg(&g_off[node + 1]);
    a0 = {0.f, 0.f}; a1 = {0.f, 0.f}; a2 = {0.f, 0.f}; a3 = {0.f, 0.f};

    const int4* c4 = reinterpret_cast<const int4*>(g_csr);
    int jq = beg >> 2, nq = (end - beg) >> 2;
    if (nq <= 0) return;

    int4 c = __ldg(&c4[jq]);
    for (int b = 1; b < nq; b++) {
        int4 cn = __ldg(&c4[jq + b]);          // prefetch next quad
        uint4 r0 = __ldg(&fp[c.x * 8 + sl]);
        uint4 r1 = __ldg(&fp[c.y * 8 + sl]);
        uint4 r2 = __ldg(&fp[c.z * 8 + sl]);
        uint4 r3 = __ldg(&fp[c.w * 8 + sl]);
        acc_row(a0, a1, a2, a3, r0);
        acc_row(a0, a1, a2, a3, r1);
        acc_row(a0, a1, a2, a3, r2);
        acc_row(a0, a1, a2, a3, r3);
        c = cn;
    }
    uint4 r0 = __ldg(&fp[c.x * 8 + sl]);
    uint4 r1 = __ldg(&fp[c.y * 8 + sl]);
    uint4 r2 = __ldg(&fp[c.z * 8 + sl]);
    uint4 r3 = __ldg(&fp[c.w * 8 + sl]);
    acc_row(a0, a1, a2, a3, r0);
    acc_row(a0, a1, a2, a3, r1);
    acc_row(a0, a1, a2, a3, r2);
    acc_row(a0, a1, a2, a3, r3);
}

// iterations k = 1..3: S_k = S_{k-1} - dis^2 * agg   (fp16 store)
__global__ void gather_kernel(int k) {
    int t = blockIdx.x * blockDim.x + threadIdx.x;
    int node = t >> 3;
    if (node >= NNODES) return;
    int sl = t & 7;

    const uint4* fp = reinterpret_cast<const uint4*>(g_feat[k - 1]);
    uint4*       fn = reinterpret_cast<uint4*>(g_feat[k]);

    float2 a0, a1, a2, a3;
    gather_accum(node, sl, fp, a0, a1, a2, a3);

    float d2 = __ldg(&g_dis2[node]);
    uint4 own = fp[node * 8 + sl];
    float2 f0 = __half22float2(*reinterpret_cast<__half2*>(&own.x));
    float2 f1 = __half22float2(*reinterpret_cast<__half2*>(&own.y));
    float2 f2 = __half22float2(*reinterpret_cast<__half2*>(&own.z));
    float2 f3 = __half22float2(*reinterpret_cast<__half2*>(&own.w));

    __half2 o0 = __floats2half2_rn(f0.x - d2 * a0.x, f0.y - d2 * a0.y);
    __half2 o1 = __floats2half2_rn(f1.x - d2 * a1.x, f1.y - d2 * a1.y);
    __half2 o2 = __floats2half2_rn(f2.x - d2 * a2.x, f2.y - d2 * a2.y);
    __half2 o3 = __floats2half2_rn(f3.x - d2 * a3.x, f3.y - d2 * a3.y);

    uint4 out;
    out.x = *reinterpret_cast<unsigned*>(&o0);
    out.y = *reinterpret_cast<unsigned*>(&o1);
    out.z = *reinterpret_cast<unsigned*>(&o2);
    out.w = *reinterpret_cast<unsigned*>(&o3);
    fn[node * 8 + sl] = out;
}

// iteration k = 4 fused with the polynomial combine:
// out = 0.6*x + invdis * (-0.4*S1 + 0.3*S2 - 0.2*S3 + 0.1*S4),  S4 = S3 - dis^2*agg
__global__ void gather_final_kernel(const float4* __restrict__ x4,
                                    float4* __restrict__ out4) {
    int t = blockIdx.x * blockDim.x + threadIdx.x;
    int node = t >> 3;
    if (node >= NNODES) return;
    int sl = t & 7;

    const uint4* fp3 = reinterpret_cast<const uint4*>(g_feat[3]);

    float2 a0, a1, a2, a3;
    gather_accum(node, sl, fp3, a0, a1, a2, a3);

    float d2 = __ldg(&g_dis2[node]);
    float inv = __ldg(&g_invdis[node]);
    int ri = node * 8 + sl;

    uint4 r3 = fp3[ri];
    uint4 r1 = reinterpret_cast<const uint4*>(g_feat[1])[ri];
    uint4 r2 = reinterpret_cast<const uint4*>(g_feat[2])[ri];

    float agg[8] = {a0.x, a0.y, a1.x, a1.y, a2.x, a2.y, a3.x, a3.y};
    unsigned w3[4] = {r3.x, r3.y, r3.z, r3.w};
    unsigned w1[4] = {r1.x, r1.y, r1.z, r1.w};
    unsigned w2[4] = {r2.x, r2.y, r2.z, r2.w};

    float4 xv0 = __ldg(&x4[node * 16 + sl * 2]);
    float4 xv1 = __ldg(&x4[node * 16 + sl * 2 + 1]);
    float xs[8] = {xv0.x, xv0.y, xv0.z, xv0.w, xv1.x, xv1.y, xv1.z, xv1.w};

    float os[8];
#pragma unroll
    for (int q = 0; q < 4; q++) {
        float2 s3 = __half22float2(*reinterpret_cast<__half2*>(&w3[q]));
        float2 s1 = __half22float2(*reinterpret_cast<__half2*>(&w1[q]));
        float2 s2 = __half22float2(*reinterpret_cast<__half2*>(&w2[q]));
        float s4x = s3.x - d2 * agg[2 * q];
        float s4y = s3.y - d2 * agg[2 * q + 1];
        float px = fmaf(0.1f, s4x, fmaf(-0.2f, s3.x, fmaf(0.3f, s2.x, -0.4f * s1.x)));
        float py = fmaf(0.1f, s4y, fmaf(-0.2f, s3.y, fmaf(0.3f, s2.y, -0.4f * s1.y)));
        os[2 * q]     = fmaf(inv, px, 0.6f * xs[2 * q]);
        os[2 * q + 1] = fmaf(inv, py, 0.6f * xs[2 * q + 1]);
    }
    float4 o0 = {os[0], os[1], os[2], os[3]};
    float4 o1 = {os[4], os[5], os[6], os[7]};
    out4[node * 16 + sl * 2]     = o0;
    out4[node * 16 + sl * 2 + 1] = o1;
}

// ---------------------------------------------------------------------------
extern "C" void kernel_launch(void* const* d_in, const int* in_sizes, int n_in,
                              void* d_out, int out_size) {
    const float4* x4 = (const float4*)d_in[0];
    const void*   ei = d_in[1];

    detect_kernel<<<1, 256>>>((const int*)ei);
    deg_kernel<<<(NEDGES / 4 + 255) / 256, 256>>>(ei);
    scan_kernel<<<NBLK, 512>>>();
    fill_init_kernel<<<(NEDGES / 4 + 255) / 256, 256>>>(ei, x4);

    const int gthreads = NNODES * 8;
    const int gblocks = (gthreads + 255) / 256;
    for (int k = 1; k <= 3; k++)
        gather_kernel<<<gblocks, 256>>>(k);
    gather_final_kernel<<<gblocks, 256>>>(x4, (float4*)d_out);
}